// round 16
// baseline (speedup 1.0000x reference)
#include <cuda_runtime.h>
#include <cuda_bf16.h>
#include <cuda_fp16.h>

#define TT 4
#define EE 2048
#define PP 512
#define DE 16
#define DH 128
#define P1 508   // P-K+1
#define P2 504   // P-2K+2

typedef unsigned long long u64;

#define G1SC 0.0009765625f   // 2^-10
#define G1SCI 1024.0f

// ---------------- scratch (device globals) ----------------
__device__ float  d_elem[TT * EE * DE];       // [t][e][16]
__device__ float  d_s0p[TT * 32 * 16];        // s0 partials [t][chunk][16]
__device__ float  d_g1[TT * EE * DH];         // g1 fp32 [t][e][d]
__device__ float  d_s1p[TT * 128 * DH];       // s1 partials [t][chunk][128]
__device__ float  d_sb[TT * DH];              // sb = s1 @ B2
__device__ __half d_c2b[TT * DH * DH];        // (A2-B2) fp16 big, [t][h][d]
__device__ __half d_c2r[TT * DH * DH];        // residual
__device__ int    d_gmax[TT * DH];            // float bits, >= 0
__device__ float  d_fpart[8 * 256];

// ---------------- helpers ----------------
__device__ __forceinline__ u64 pack2(float a, float b) {
    u64 r; asm("mov.b64 %0, {%1, %2};" : "=l"(r) : "f"(a), "f"(b)); return r;
}
__device__ __forceinline__ void unpack2(u64 v, float& a, float& b) {
    asm("mov.b64 {%0, %1}, %2;" : "=f"(a), "=f"(b) : "l"(v));
}
__device__ __forceinline__ void fma2(u64& d, u64 a, u64 b) {
    asm("fma.rn.f32x2 %0, %1, %2, %0;" : "+l"(d) : "l"(a), "l"(b));
}
__device__ __forceinline__ unsigned h2bits(__half2 v) {
    return *reinterpret_cast<unsigned*>(&v);
}

// ---------------- fp16 mma m16n8k16 (A row, B col, fp32 acc) ----------------
__device__ __forceinline__ void mma_f16(float* c,
    unsigned a0, unsigned a1, unsigned a2, unsigned a3,
    unsigned b0, unsigned b1)
{
    asm volatile(
        "mma.sync.aligned.m16n8k16.row.col.f32.f16.f16.f32 "
        "{%0,%1,%2,%3}, {%4,%5,%6,%7}, {%8,%9}, {%0,%1,%2,%3};"
        : "+f"(c[0]), "+f"(c[1]), "+f"(c[2]), "+f"(c[3])
        : "r"(a0), "r"(a1), "r"(a2), "r"(a3), "r"(b0), "r"(b1));
}

// ---------------- K0: precompute C2 = A2-B2 split fp16, [t][h][d] ----------------
// grid TT, block 256 (j = dword 0..63, hg = 4 groups of 32 h)
__global__ __launch_bounds__(256) void k_prep(
    const float* __restrict__ A2, const float* __restrict__ B2)
{
    const int t = blockIdx.x;
    const int j = threadIdx.x & 63;
    const int hg = threadIdx.x >> 6;
    unsigned* cb = reinterpret_cast<unsigned*>(d_c2b) + t * 8192;
    unsigned* cr = reinterpret_cast<unsigned*>(d_c2r) + t * 8192;
    const float* a2 = A2 + t * 16384;
    const float* b2 = B2 + t * 16384;
    #pragma unroll 4
    for (int hh = 0; hh < 32; hh++) {
        int h = hg * 32 + hh;
        float v0 = a2[(2 * j) * 128 + h]     - b2[(2 * j) * 128 + h];
        float v1 = a2[(2 * j + 1) * 128 + h] - b2[(2 * j + 1) * 128 + h];
        __half bh0 = __float2half_rn(v0), bh1 = __float2half_rn(v1);
        __half2 big = __halves2half2(bh0, bh1);   // low = even d
        __half2 res = __halves2half2(__float2half_rn(v0 - __half2float(bh0)),
                                     __float2half_rn(v1 - __half2float(bh1)));
        cb[h * 64 + j] = h2bits(big);
        cr[h * 64 + j] = h2bits(res);
    }
}

// ---------------- K1: conv1 (f32x2) + conv2 (fp16 HMMA, W-split), 2 e's per CTA ----------------
// grid (E/2, T), block 128   (unchanged — passing since R14)
__global__ __launch_bounds__(128) void k_conv(
    const float* __restrict__ points,
    const float* __restrict__ w1, const float* __restrict__ b1,
    const float* __restrict__ w2, const float* __restrict__ b2)
{
    __shared__ __align__(16) __half h1h[520 * 18];
    __shared__ float pts[2][PP];
    __shared__ __align__(4) __half w2b[1280];
    __shared__ __align__(4) __half w2r[1280];
    __shared__ float w1s[160];
    __shared__ float b1s[16], b2s[16];
    __shared__ float redw[4][16];

    const int tid = threadIdx.x;
    const int t = blockIdx.y, e0 = blockIdx.x * 2;

    unsigned* h1h32 = reinterpret_cast<unsigned*>(h1h);

    const float2* pin2 = reinterpret_cast<const float2*>(points + (size_t)(t * EE + e0) * PP * 2);
    #pragma unroll
    for (int j = 0; j < 4; j++) {
        int p = tid + j * 128;
        float2 v = pin2[p];
        pts[0][p] = v.x; pts[1][p] = v.y;
    }
    for (int i = tid; i < 160; i += 128) w1s[i] = w1[t * 160 + i];
    for (int i = tid; i < 1280; i += 128) {
        float v = w2[t * 1280 + i];
        int co = i / 80, rem = i % 80, ci = rem / 5, s = rem % 5;
        __half b = __float2half_rn(v);
        float r = v - __half2float(b);
        w2b[(co * 5 + s) * 16 + ci] = b;
        w2r[(co * 5 + s) * 16 + ci] = __float2half_rn(r);
    }
    if (tid < 16) { b1s[tid] = b1[t * 16 + tid]; b2s[tid] = b2[t * 16 + tid]; }
    __syncthreads();

    const int lane = tid & 31, wrp = tid >> 5;
    const int g = lane >> 2, tq = lane & 3;
    const float b2g = b2s[g], b2g8 = b2s[g + 8];

    #pragma unroll 1
    for (int sub = 0; sub < 2; sub++) {
        u64 xp[2][5], yp[2][5];
        #pragma unroll
        for (int pr = 0; pr < 2; pr++) {
            int pA = tid + (2 * pr) * 128;
            int pB = tid + (2 * pr + 1) * 128;
            int pAc = (pA < P1) ? pA : (P1 - 1);
            int pBc = (pB < P1) ? pB : (P1 - 1);
            #pragma unroll
            for (int k = 0; k < 5; k++) {
                xp[pr][k] = pack2(pts[0][pAc + k], pts[0][pBc + k]);
                yp[pr][k] = pack2(pts[1][pAc + k], pts[1][pBc + k]);
            }
        }
        float2 pv[4];
        if (sub == 0) {
            const float2* pin2b = reinterpret_cast<const float2*>(
                points + (size_t)(t * EE + e0 + 1) * PP * 2);
            #pragma unroll
            for (int j = 0; j < 4; j++) pv[j] = pin2b[tid + j * 128];
        }

        const bool m1 = (tid + 384 < P1);
        #pragma unroll 1
        for (int cp = 0; cp < 8; cp++) {
            float wA[10], wB[10];
            #pragma unroll
            for (int q = 0; q < 10; q++) {
                wA[q] = w1s[(2 * cp) * 10 + q];
                wB[q] = w1s[(2 * cp + 1) * 10 + q];
            }
            float bbA = b1s[2 * cp], bbB = b1s[2 * cp + 1];
            u64 aA0 = pack2(bbA, bbA), aA1 = aA0;
            u64 aB0 = pack2(bbB, bbB), aB1 = aB0;
            #pragma unroll
            for (int k = 0; k < 5; k++) {
                u64 wa = pack2(wA[k], wA[k]);
                fma2(aA0, wa, xp[0][k]); fma2(aA1, wa, xp[1][k]);
                u64 wb = pack2(wB[k], wB[k]);
                fma2(aB0, wb, xp[0][k]); fma2(aB1, wb, xp[1][k]);
            }
            #pragma unroll
            for (int k = 0; k < 5; k++) {
                u64 wa = pack2(wA[5 + k], wA[5 + k]);
                fma2(aA0, wa, yp[0][k]); fma2(aA1, wa, yp[1][k]);
                u64 wb = pack2(wB[5 + k], wB[5 + k]);
                fma2(aB0, wb, yp[0][k]); fma2(aB1, wb, yp[1][k]);
            }
            float vA[4], vB[4];
            unpack2(aA0, vA[0], vA[1]); unpack2(aA1, vA[2], vA[3]);
            unpack2(aB0, vB[0], vB[1]); unpack2(aB1, vB[2], vB[3]);
            #pragma unroll
            for (int j = 0; j < 4; j++) {
                if (j == 3 && !m1) break;
                int p = tid + j * 128;
                float a = fmaxf(vA[j], 0.f), b = fmaxf(vB[j], 0.f);
                __half2 hv = __floats2half2_rn(a, b);
                h1h32[p * 9 + cp] = h2bits(hv);
            }
        }
        __syncthreads();

        if (sub == 0) {
            #pragma unroll
            for (int j = 0; j < 4; j++) {
                int p = tid + j * 128;
                pts[0][p] = pv[j].x; pts[1][p] = pv[j].y;
            }
        }

        float acc[16][4];
        #pragma unroll
        for (int i = 0; i < 16; i++) {
            acc[i][0] = 0.f; acc[i][1] = 0.f; acc[i][2] = 0.f; acc[i][3] = 0.f;
        }
        const unsigned* w2b32 = reinterpret_cast<const unsigned*>(w2b);
        const unsigned* w2r32 = reinterpret_cast<const unsigned*>(w2r);

        #pragma unroll
        for (int s = 0; s < 5; s++) {
            const int awl = (g * 5 + s) * 8 + tq;
            const int awh = ((g + 8) * 5 + s) * 8 + tq;
            unsigned ab0 = w2b32[awl],     ab1 = w2b32[awh];
            unsigned ab2 = w2b32[awl + 4], ab3 = w2b32[awh + 4];
            unsigned ar0 = w2r32[awl],     ar1 = w2r32[awh];
            unsigned ar2 = w2r32[awl + 4], ar3 = w2r32[awh + 4];
            #pragma unroll
            for (int i = 0; i < 16; i++) {
                int nb = wrp + 4 * i;
                if (nb >= 63) break;
                int pw = (nb * 8 + g + s) * 9 + tq;
                unsigned bb0 = h1h32[pw], bb1 = h1h32[pw + 4];
                mma_f16(acc[i], ab0, ab1, ab2, ab3, bb0, bb1);
                mma_f16(acc[i], ar0, ar1, ar2, ar3, bb0, bb1);
            }
        }

        float sg = 0.f, sg8 = 0.f;
        #pragma unroll
        for (int i = 0; i < 16; i++) {
            int nb = wrp + 4 * i;
            if (nb >= 63) break;
            sg  += fmaxf(acc[i][0] + b2g, 0.f)  + fmaxf(acc[i][1] + b2g, 0.f);
            sg8 += fmaxf(acc[i][2] + b2g8, 0.f) + fmaxf(acc[i][3] + b2g8, 0.f);
        }
        sg  += __shfl_xor_sync(0xffffffffu, sg, 1);
        sg  += __shfl_xor_sync(0xffffffffu, sg, 2);
        sg8 += __shfl_xor_sync(0xffffffffu, sg8, 1);
        sg8 += __shfl_xor_sync(0xffffffffu, sg8, 2);
        if (tq == 0) { redw[wrp][g] = sg; redw[wrp][g + 8] = sg8; }
        __syncthreads();
        if (tid < 16)
            d_elem[(size_t)(t * EE + e0 + sub) * 16 + tid] =
                redw[0][tid] + redw[1][tid] + redw[2][tid] + redw[3][tid];
    }
}

// ---------------- K2: s0 partials (+zero gmax)  grid (32, T), block 256 ----------------
__global__ __launch_bounds__(256) void k_s0p() {
    const int t = blockIdx.y, chunk = blockIdx.x, tid = threadIdx.x;
    const int d = tid & 15, grp = tid >> 4;
    const int e0 = chunk * 64;
    float acc = 0.f;
    #pragma unroll
    for (int i = 0; i < 4; i++)
        acc += d_elem[(size_t)(t * EE + e0 + grp + 16 * i) * 16 + d];
    __shared__ float r[256];
    r[tid] = acc; __syncthreads();
    if (tid < 128) r[tid] += r[tid + 128];
    __syncthreads();
    if (tid < 64) r[tid] += r[tid + 64];
    __syncthreads();
    if (tid < 32) r[tid] += r[tid + 32];
    __syncthreads();
    if (tid < 16) d_s0p[(t * 32 + chunk) * 16 + tid] = r[tid] + r[tid + 16];
    if (chunk == 0 && tid < 128) d_gmax[t * 128 + tid] = 0;
}

// ---------------- K3: layer1 -> d_g1 (fp32) + s1 partials  grid (128, T), block 256 ----------------
__global__ __launch_bounds__(256) void k_l1(
    const float* __restrict__ A1, const float* __restrict__ B1)
{
    __shared__ float C1s[16][128];
    __shared__ float elems[16][16];
    __shared__ float r[256];
    __shared__ float s0s[16];

    const int tid = threadIdx.x, t = blockIdx.y, chunk = blockIdx.x;
    const int e0 = chunk * 16;
    const int h = tid & 127, half = tid >> 7;

    elems[tid >> 4][tid & 15] = d_elem[(size_t)(t * EE + e0) * 16 + tid];
    for (int i = tid; i < 2048; i += 256)
        C1s[i >> 7][i & 127] = A1[t * 2048 + i] - B1[t * 2048 + i];
    if (tid < 16) {
        float s = 0.f;
        #pragma unroll
        for (int b = 0; b < 32; b++) s += d_s0p[(t * 32 + b) * 16 + tid];
        s0s[tid] = s;
    }
    __syncthreads();

    float c1r[16];
    #pragma unroll
    for (int d = 0; d < 16; d++) c1r[d] = C1s[d][h];
    float sbl1 = 0.f;
    #pragma unroll
    for (int d = 0; d < 16; d++)
        sbl1 = fmaf(s0s[d], B1[t * 2048 + d * 128 + h], sbl1);

    float accs = 0.f;
    const int eib = half * 8;
    #pragma unroll
    for (int ei = 0; ei < 8; ei++) {
        float v = sbl1;
        #pragma unroll
        for (int d = 0; d < 16; d++) v = fmaf(elems[eib + ei][d], c1r[d], v);
        v = fmaxf(v, 0.f);
        d_g1[(size_t)(t * EE + e0 + eib + ei) * 128 + h] = v;
        accs += v;
    }
    r[tid] = accs;
    __syncthreads();
    if (tid < 128)
        d_s1p[(t * 128 + chunk) * 128 + tid] = r[tid] + r[tid + 128];
}

// ---------------- K3b: combine s1 partials + sb = s1 @ B2  grid (T), block 512 ----------------
__global__ __launch_bounds__(512) void k_s1c(const float* __restrict__ B2) {
    const int t = blockIdx.x, tid = threadIdx.x;
    const int h = tid & 127, q = tid >> 7;
    __shared__ float r[512];
    __shared__ float s1sm[128];
    float s = 0.f;
    #pragma unroll 8
    for (int i = 0; i < 32; i++)
        s += d_s1p[(t * 128 + q * 32 + i) * 128 + h];
    r[tid] = s; __syncthreads();
    if (tid < 128) s1sm[tid] = r[tid] + r[tid + 128] + r[tid + 256] + r[tid + 384];
    __syncthreads();
    float sbp = 0.f;
    #pragma unroll 8
    for (int i = 0; i < 32; i++) {
        int d = q * 32 + i;
        sbp = fmaf(s1sm[d], B2[t * 16384 + d * 128 + h], sbp);
    }
    r[tid] = sbp; __syncthreads();
    if (tid < 128)
        d_sb[t * 128 + tid] = r[tid] + r[tid + 128] + r[tid + 256] + r[tid + 384];
}

// ---------------- K4: layer2 via fp16 HMMA (scaled g1 split) + max  grid (64, T), block 256 ----------------
__global__ __launch_bounds__(256) void k_l2() {
    __shared__ __align__(16) unsigned g1b[32 * 68];   // [e][dword], big (scaled)
    __shared__ __align__(16) unsigned g1r[32 * 68];   // residual
    __shared__ float sbs[128];

    const int tid = threadIdx.x, t = blockIdx.y, chunk = blockIdx.x;
    const int e0 = chunk * 32;

    const float2* gsrc = reinterpret_cast<const float2*>(d_g1 + (size_t)(t * EE + e0) * 128);
    for (int i = tid; i < 2048; i += 256) {
        int e = i >> 6, j = i & 63;
        float2 v = gsrc[e * 64 + j];
        float v0 = v.x * G1SC, v1 = v.y * G1SC;
        __half b0 = __float2half_rn(v0), b1 = __float2half_rn(v1);
        __half2 big = __halves2half2(b0, b1);   // low = even d
        __half2 res = __halves2half2(__float2half_rn(v0 - __half2float(b0)),
                                     __float2half_rn(v1 - __half2float(b1)));
        g1b[e * 68 + j] = h2bits(big);
        g1r[e * 68 + j] = h2bits(res);
    }
    if (tid < 128) sbs[tid] = d_sb[t * 128 + tid];
    __syncthreads();

    const int lane = tid & 31, wrp = tid >> 5;
    const int g = lane >> 2, tq = lane & 3;
    const int h0 = wrp * 16;
    const unsigned* cb = reinterpret_cast<const unsigned*>(d_c2b) + t * 8192;
    const unsigned* cr = reinterpret_cast<const unsigned*>(d_c2r) + t * 8192;

    float acc[2][2][4];
    #pragma unroll
    for (int mt = 0; mt < 2; mt++)
        #pragma unroll
        for (int nt = 0; nt < 2; nt++) {
            acc[mt][nt][0] = 0.f; acc[mt][nt][1] = 0.f;
            acc[mt][nt][2] = 0.f; acc[mt][nt][3] = 0.f;
        }

    #pragma unroll
    for (int kb = 0; kb < 8; kb++) {
        const int aw = kb * 8 + tq;
        // big A frags (rows e: g, g+8 | 16+g, 24+g)
        unsigned a00 = g1b[g * 68 + aw],            a01 = g1b[(g + 8) * 68 + aw];
        unsigned a02 = g1b[g * 68 + aw + 4],        a03 = g1b[(g + 8) * 68 + aw + 4];
        unsigned a10 = g1b[(16 + g) * 68 + aw],     a11 = g1b[(24 + g) * 68 + aw];
        unsigned a12 = g1b[(16 + g) * 68 + aw + 4], a13 = g1b[(24 + g) * 68 + aw + 4];
        // residual A frags
        unsigned r00 = g1r[g * 68 + aw],            r01 = g1r[(g + 8) * 68 + aw];
        unsigned r02 = g1r[g * 68 + aw + 4],        r03 = g1r[(g + 8) * 68 + aw + 4];
        unsigned r10 = g1r[(16 + g) * 68 + aw],     r11 = g1r[(24 + g) * 68 + aw];
        unsigned r12 = g1r[(16 + g) * 68 + aw + 4], r13 = g1r[(24 + g) * 68 + aw + 4];
        #pragma unroll
        for (int nt = 0; nt < 2; nt++) {
            int h = h0 + nt * 8 + g;
            unsigned b0 = cb[h * 64 + aw], b1 = cb[h * 64 + aw + 4];
            unsigned q0 = cr[h * 64 + aw], q1 = cr[h * 64 + aw + 4];
            mma_f16(acc[0][nt], a00, a01, a02, a03, b0, b1);   // gb*Cb
            mma_f16(acc[1][nt], a10, a11, a12, a13, b0, b1);
            mma_f16(acc[0][nt], a00, a01, a02, a03, q0, q1);   // gb*Cr
            mma_f16(acc[1][nt], a10, a11, a12, a13, q0, q1);
            mma_f16(acc[0][nt], r00, r01, r02, r03, b0, b1);   // gr*Cb
            mma_f16(acc[1][nt], r10, r11, r12, r13, b0, b1);
        }
    }

    // epilogue: max over 32 e's (scaled domain), unscale, add sb, relu, atomicMax
    #pragma unroll
    for (int nt = 0; nt < 2; nt++) {
        float m0 = fmaxf(fmaxf(acc[0][nt][0], acc[0][nt][2]),
                         fmaxf(acc[1][nt][0], acc[1][nt][2]));
        float m1 = fmaxf(fmaxf(acc[0][nt][1], acc[0][nt][3]),
                         fmaxf(acc[1][nt][1], acc[1][nt][3]));
        #pragma unroll
        for (int off = 4; off < 32; off <<= 1) {
            m0 = fmaxf(m0, __shfl_xor_sync(0xffffffffu, m0, off));
            m1 = fmaxf(m1, __shfl_xor_sync(0xffffffffu, m1, off));
        }
        if (g == 0) {
            int h = h0 + nt * 8 + tq * 2;
            atomicMax(&d_gmax[t * 128 + h],
                      __float_as_int(fmaxf(fmaf(m0, G1SCI, sbs[h]), 0.f)));
            atomicMax(&d_gmax[t * 128 + h + 1],
                      __float_as_int(fmaxf(fmaf(m1, G1SCI, sbs[h + 1]), 0.f)));
        }
    }
}

// ---------------- K5: gf + final matmul partials  grid 8, block 256 ----------------
__global__ __launch_bounds__(256) void k_gfw(const float* __restrict__ Aout,
                                             const float* __restrict__ Wm)
{
    __shared__ float gv[512];
    __shared__ float gfs[64];
    __shared__ float r[256];
    const int tid = threadIdx.x, blk = blockIdx.x;

    for (int i = tid; i < 512; i += 256) gv[i] = __int_as_float(d_gmax[i]);
    __syncthreads();

    const int j = tid >> 2, sub = tid & 3;
    const int gi = blk * 64 + j;
    const int t2 = gi >> 7, o = gi & 127;
    float a = 0.f;
    #pragma unroll 4
    for (int k = 0; k < 32; k++)
        a = fmaf(gv[t2 * 128 + sub * 32 + k],
                 Aout[t2 * 16384 + (sub * 32 + k) * 128 + o], a);
    r[tid] = a;
    __syncthreads();
    if (sub == 0) gfs[j] = r[tid] + r[tid + 1] + r[tid + 2] + r[tid + 3];
    __syncthreads();

    float acc = 0.f;
    const int i0 = blk * 64;
    #pragma unroll 8
    for (int i = 0; i < 64; i++)
        acc = fmaf(gfs[i], Wm[(i0 + i) * 256 + tid], acc);
    d_fpart[blk * 256 + tid] = acc;
}

// ---------------- K6: combine  grid 1, block 256 ----------------
__global__ void k_fin2(const float* __restrict__ bm, float* __restrict__ out) {
    const int tid = threadIdx.x;
    float a = bm[tid];
    #pragma unroll
    for (int b = 0; b < 8; b++) a += d_fpart[b * 256 + tid];
    out[tid] = a;
}

// ---------------- launch ----------------
extern "C" void kernel_launch(void* const* d_in, const int* in_sizes, int n_in,
                              void* d_out, int out_size)
{
    const float* points = (const float*)d_in[0];
    const float* w1     = (const float*)d_in[1];
    const float* b1     = (const float*)d_in[2];
    const float* w2     = (const float*)d_in[3];
    const float* b2     = (const float*)d_in[4];
    const float* A1     = (const float*)d_in[5];
    const float* B1     = (const float*)d_in[6];
    const float* A2     = (const float*)d_in[7];
    const float* B2     = (const float*)d_in[8];
    const float* Aout   = (const float*)d_in[9];
    const float* Wm     = (const float*)d_in[10];
    const float* bm     = (const float*)d_in[11];
    float* out = (float*)d_out;

    k_prep<<<TT, 256>>>(A2, B2);
    k_conv<<<dim3(EE / 2, TT), 128>>>(points, w1, b1, w2, b2);
    k_s0p<<<dim3(32, TT), 256>>>();
    k_l1<<<dim3(128, TT), 256>>>(A1, B1);
    k_s1c<<<TT, 512>>>(B2);
    k_l2<<<dim3(64, TT), 256>>>();
    k_gfw<<<8, 256>>>(Aout, Wm);
    k_fin2<<<1, 256>>>(bm, out);
}

// round 17
// speedup vs baseline: 1.1034x; 1.1034x over previous
#include <cuda_runtime.h>
#include <cuda_bf16.h>
#include <cuda_fp16.h>

#define TT 4
#define EE 2048
#define PP 512
#define DE 16
#define DH 128
#define P1 508   // P-K+1
#define P2 504   // P-2K+2

typedef unsigned long long u64;

#define G1SC 0.0009765625f   // 2^-10
#define G1SCI 1024.0f

// ---------------- scratch (device globals) ----------------
__device__ float  d_elem[TT * EE * DE];       // [t][e][16]
__device__ float  d_s0p[TT * 32 * 16];        // s0 partials [t][chunk][16]
__device__ float  d_g1[TT * EE * DH];         // g1 fp32 [t][e][d]
__device__ float  d_s1p[TT * 128 * DH];       // s1 partials [t][chunk][128]
__device__ float  d_sb[TT * DH];              // sb = s1 @ B2
__device__ __half d_c2b[TT * DH * DH];        // (A2-B2) fp16 big, [t][h][d]
__device__ __half d_c2r[TT * DH * DH];        // residual
__device__ int    d_gmax[TT * DH];            // float bits, >= 0
__device__ float  d_fpart[8 * 256];

// ---------------- helpers ----------------
__device__ __forceinline__ u64 pack2(float a, float b) {
    u64 r; asm("mov.b64 %0, {%1, %2};" : "=l"(r) : "f"(a), "f"(b)); return r;
}
__device__ __forceinline__ void unpack2(u64 v, float& a, float& b) {
    asm("mov.b64 {%0, %1}, %2;" : "=f"(a), "=f"(b) : "l"(v));
}
__device__ __forceinline__ void fma2(u64& d, u64 a, u64 b) {
    asm("fma.rn.f32x2 %0, %1, %2, %0;" : "+l"(d) : "l"(a), "l"(b));
}
__device__ __forceinline__ unsigned h2bits(__half2 v) {
    return *reinterpret_cast<unsigned*>(&v);
}

// ---------------- fp16 mma m16n8k16 (A row, B col, fp32 acc) ----------------
__device__ __forceinline__ void mma_f16(float* c,
    unsigned a0, unsigned a1, unsigned a2, unsigned a3,
    unsigned b0, unsigned b1)
{
    asm volatile(
        "mma.sync.aligned.m16n8k16.row.col.f32.f16.f16.f32 "
        "{%0,%1,%2,%3}, {%4,%5,%6,%7}, {%8,%9}, {%0,%1,%2,%3};"
        : "+f"(c[0]), "+f"(c[1]), "+f"(c[2]), "+f"(c[3])
        : "r"(a0), "r"(a1), "r"(a2), "r"(a3), "r"(b0), "r"(b1));
}

// ---------------- K0: precompute C2 = A2-B2 split fp16, [t][h][d] ----------------
// grid (16, TT), block 256: chunk handles 8 h rows
__global__ __launch_bounds__(256) void k_prep(
    const float* __restrict__ A2, const float* __restrict__ B2)
{
    const int t = blockIdx.y, chunk = blockIdx.x, tid = threadIdx.x;
    unsigned* cb = reinterpret_cast<unsigned*>(d_c2b) + t * 8192;
    unsigned* cr = reinterpret_cast<unsigned*>(d_c2r) + t * 8192;
    const float* a2 = A2 + t * 16384;
    const float* b2 = B2 + t * 16384;
    #pragma unroll
    for (int i = tid; i < 512; i += 256) {
        int h = chunk * 8 + (i >> 6);
        int j = i & 63;
        float v0 = a2[(2 * j) * 128 + h]     - b2[(2 * j) * 128 + h];
        float v1 = a2[(2 * j + 1) * 128 + h] - b2[(2 * j + 1) * 128 + h];
        __half bh0 = __float2half_rn(v0), bh1 = __float2half_rn(v1);
        __half2 big = __halves2half2(bh0, bh1);   // low = even d
        __half2 res = __halves2half2(__float2half_rn(v0 - __half2float(bh0)),
                                     __float2half_rn(v1 - __half2float(bh1)));
        cb[h * 64 + j] = h2bits(big);
        cr[h * 64 + j] = h2bits(res);
    }
}

// ---------------- K1: conv1 (f32x2) + conv2 (fp16 HMMA, W-split), 2 e's per CTA ----------------
// grid (E/2, T), block 128   (unchanged — passing since R14)
__global__ __launch_bounds__(128) void k_conv(
    const float* __restrict__ points,
    const float* __restrict__ w1, const float* __restrict__ b1,
    const float* __restrict__ w2, const float* __restrict__ b2)
{
    __shared__ __align__(16) __half h1h[520 * 18];
    __shared__ float pts[2][PP];
    __shared__ __align__(4) __half w2b[1280];
    __shared__ __align__(4) __half w2r[1280];
    __shared__ float w1s[160];
    __shared__ float b1s[16], b2s[16];
    __shared__ float redw[4][16];

    const int tid = threadIdx.x;
    const int t = blockIdx.y, e0 = blockIdx.x * 2;

    unsigned* h1h32 = reinterpret_cast<unsigned*>(h1h);

    const float2* pin2 = reinterpret_cast<const float2*>(points + (size_t)(t * EE + e0) * PP * 2);
    #pragma unroll
    for (int j = 0; j < 4; j++) {
        int p = tid + j * 128;
        float2 v = pin2[p];
        pts[0][p] = v.x; pts[1][p] = v.y;
    }
    for (int i = tid; i < 160; i += 128) w1s[i] = w1[t * 160 + i];
    for (int i = tid; i < 1280; i += 128) {
        float v = w2[t * 1280 + i];
        int co = i / 80, rem = i % 80, ci = rem / 5, s = rem % 5;
        __half b = __float2half_rn(v);
        float r = v - __half2float(b);
        w2b[(co * 5 + s) * 16 + ci] = b;
        w2r[(co * 5 + s) * 16 + ci] = __float2half_rn(r);
    }
    if (tid < 16) { b1s[tid] = b1[t * 16 + tid]; b2s[tid] = b2[t * 16 + tid]; }
    __syncthreads();

    const int lane = tid & 31, wrp = tid >> 5;
    const int g = lane >> 2, tq = lane & 3;
    const float b2g = b2s[g], b2g8 = b2s[g + 8];

    #pragma unroll 1
    for (int sub = 0; sub < 2; sub++) {
        u64 xp[2][5], yp[2][5];
        #pragma unroll
        for (int pr = 0; pr < 2; pr++) {
            int pA = tid + (2 * pr) * 128;
            int pB = tid + (2 * pr + 1) * 128;
            int pAc = (pA < P1) ? pA : (P1 - 1);
            int pBc = (pB < P1) ? pB : (P1 - 1);
            #pragma unroll
            for (int k = 0; k < 5; k++) {
                xp[pr][k] = pack2(pts[0][pAc + k], pts[0][pBc + k]);
                yp[pr][k] = pack2(pts[1][pAc + k], pts[1][pBc + k]);
            }
        }
        float2 pv[4];
        if (sub == 0) {
            const float2* pin2b = reinterpret_cast<const float2*>(
                points + (size_t)(t * EE + e0 + 1) * PP * 2);
            #pragma unroll
            for (int j = 0; j < 4; j++) pv[j] = pin2b[tid + j * 128];
        }

        const bool m1 = (tid + 384 < P1);
        #pragma unroll 1
        for (int cp = 0; cp < 8; cp++) {
            float wA[10], wB[10];
            #pragma unroll
            for (int q = 0; q < 10; q++) {
                wA[q] = w1s[(2 * cp) * 10 + q];
                wB[q] = w1s[(2 * cp + 1) * 10 + q];
            }
            float bbA = b1s[2 * cp], bbB = b1s[2 * cp + 1];
            u64 aA0 = pack2(bbA, bbA), aA1 = aA0;
            u64 aB0 = pack2(bbB, bbB), aB1 = aB0;
            #pragma unroll
            for (int k = 0; k < 5; k++) {
                u64 wa = pack2(wA[k], wA[k]);
                fma2(aA0, wa, xp[0][k]); fma2(aA1, wa, xp[1][k]);
                u64 wb = pack2(wB[k], wB[k]);
                fma2(aB0, wb, xp[0][k]); fma2(aB1, wb, xp[1][k]);
            }
            #pragma unroll
            for (int k = 0; k < 5; k++) {
                u64 wa = pack2(wA[5 + k], wA[5 + k]);
                fma2(aA0, wa, yp[0][k]); fma2(aA1, wa, yp[1][k]);
                u64 wb = pack2(wB[5 + k], wB[5 + k]);
                fma2(aB0, wb, yp[0][k]); fma2(aB1, wb, yp[1][k]);
            }
            float vA[4], vB[4];
            unpack2(aA0, vA[0], vA[1]); unpack2(aA1, vA[2], vA[3]);
            unpack2(aB0, vB[0], vB[1]); unpack2(aB1, vB[2], vB[3]);
            #pragma unroll
            for (int j = 0; j < 4; j++) {
                if (j == 3 && !m1) break;
                int p = tid + j * 128;
                float a = fmaxf(vA[j], 0.f), b = fmaxf(vB[j], 0.f);
                __half2 hv = __floats2half2_rn(a, b);
                h1h32[p * 9 + cp] = h2bits(hv);
            }
        }
        __syncthreads();

        if (sub == 0) {
            #pragma unroll
            for (int j = 0; j < 4; j++) {
                int p = tid + j * 128;
                pts[0][p] = pv[j].x; pts[1][p] = pv[j].y;
            }
        }

        float acc[16][4];
        #pragma unroll
        for (int i = 0; i < 16; i++) {
            acc[i][0] = 0.f; acc[i][1] = 0.f; acc[i][2] = 0.f; acc[i][3] = 0.f;
        }
        const unsigned* w2b32 = reinterpret_cast<const unsigned*>(w2b);
        const unsigned* w2r32 = reinterpret_cast<const unsigned*>(w2r);

        #pragma unroll
        for (int s = 0; s < 5; s++) {
            const int awl = (g * 5 + s) * 8 + tq;
            const int awh = ((g + 8) * 5 + s) * 8 + tq;
            unsigned ab0 = w2b32[awl],     ab1 = w2b32[awh];
            unsigned ab2 = w2b32[awl + 4], ab3 = w2b32[awh + 4];
            unsigned ar0 = w2r32[awl],     ar1 = w2r32[awh];
            unsigned ar2 = w2r32[awl + 4], ar3 = w2r32[awh + 4];
            #pragma unroll
            for (int i = 0; i < 16; i++) {
                int nb = wrp + 4 * i;
                if (nb >= 63) break;
                int pw = (nb * 8 + g + s) * 9 + tq;
                unsigned bb0 = h1h32[pw], bb1 = h1h32[pw + 4];
                mma_f16(acc[i], ab0, ab1, ab2, ab3, bb0, bb1);
                mma_f16(acc[i], ar0, ar1, ar2, ar3, bb0, bb1);
            }
        }

        float sg = 0.f, sg8 = 0.f;
        #pragma unroll
        for (int i = 0; i < 16; i++) {
            int nb = wrp + 4 * i;
            if (nb >= 63) break;
            sg  += fmaxf(acc[i][0] + b2g, 0.f)  + fmaxf(acc[i][1] + b2g, 0.f);
            sg8 += fmaxf(acc[i][2] + b2g8, 0.f) + fmaxf(acc[i][3] + b2g8, 0.f);
        }
        sg  += __shfl_xor_sync(0xffffffffu, sg, 1);
        sg  += __shfl_xor_sync(0xffffffffu, sg, 2);
        sg8 += __shfl_xor_sync(0xffffffffu, sg8, 1);
        sg8 += __shfl_xor_sync(0xffffffffu, sg8, 2);
        if (tq == 0) { redw[wrp][g] = sg; redw[wrp][g + 8] = sg8; }
        __syncthreads();
        if (tid < 16)
            d_elem[(size_t)(t * EE + e0 + sub) * 16 + tid] =
                redw[0][tid] + redw[1][tid] + redw[2][tid] + redw[3][tid];
    }
}

// ---------------- K2: s0 partials (+zero gmax)  grid (32, T), block 256 ----------------
__global__ __launch_bounds__(256) void k_s0p() {
    const int t = blockIdx.y, chunk = blockIdx.x, tid = threadIdx.x;
    const int d = tid & 15, grp = tid >> 4;
    const int e0 = chunk * 64;
    float acc = 0.f;
    #pragma unroll
    for (int i = 0; i < 4; i++)
        acc += d_elem[(size_t)(t * EE + e0 + grp + 16 * i) * 16 + d];
    __shared__ float r[256];
    r[tid] = acc; __syncthreads();
    if (tid < 128) r[tid] += r[tid + 128];
    __syncthreads();
    if (tid < 64) r[tid] += r[tid + 64];
    __syncthreads();
    if (tid < 32) r[tid] += r[tid + 32];
    __syncthreads();
    if (tid < 16) d_s0p[(t * 32 + chunk) * 16 + tid] = r[tid] + r[tid + 16];
    if (chunk == 0 && tid < 128) d_gmax[t * 128 + tid] = 0;
}

// ---------------- K3: layer1 -> d_g1 (fp32) + s1 partials  grid (128, T), block 256 ----------------
__global__ __launch_bounds__(256) void k_l1(
    const float* __restrict__ A1, const float* __restrict__ B1)
{
    __shared__ float C1s[16][128];
    __shared__ float elems[16][16];
    __shared__ float r[256];
    __shared__ float s0s[16];

    const int tid = threadIdx.x, t = blockIdx.y, chunk = blockIdx.x;
    const int e0 = chunk * 16;
    const int h = tid & 127, half = tid >> 7;

    elems[tid >> 4][tid & 15] = d_elem[(size_t)(t * EE + e0) * 16 + tid];
    for (int i = tid; i < 2048; i += 256)
        C1s[i >> 7][i & 127] = A1[t * 2048 + i] - B1[t * 2048 + i];
    if (tid < 16) {
        float s = 0.f;
        #pragma unroll
        for (int b = 0; b < 32; b++) s += d_s0p[(t * 32 + b) * 16 + tid];
        s0s[tid] = s;
    }
    __syncthreads();

    float c1r[16];
    #pragma unroll
    for (int d = 0; d < 16; d++) c1r[d] = C1s[d][h];
    float sbl1 = 0.f;
    #pragma unroll
    for (int d = 0; d < 16; d++)
        sbl1 = fmaf(s0s[d], B1[t * 2048 + d * 128 + h], sbl1);

    float accs = 0.f;
    const int eib = half * 8;
    #pragma unroll
    for (int ei = 0; ei < 8; ei++) {
        float v = sbl1;
        #pragma unroll
        for (int d = 0; d < 16; d++) v = fmaf(elems[eib + ei][d], c1r[d], v);
        v = fmaxf(v, 0.f);
        d_g1[(size_t)(t * EE + e0 + eib + ei) * 128 + h] = v;
        accs += v;
    }
    r[tid] = accs;
    __syncthreads();
    if (tid < 128)
        d_s1p[(t * 128 + chunk) * 128 + tid] = r[tid] + r[tid + 128];
}

// ---------------- K3b: s1 combine + sb slice  grid (4, T), block 512 ----------------
__global__ __launch_bounds__(512) void k_s1c(const float* __restrict__ B2) {
    const int q = blockIdx.x, t = blockIdx.y, tid = threadIdx.x;
    __shared__ float r[512];
    __shared__ float s1sm[128];

    // full s1 combine (redundant per block; L2-hot)
    {
        const int h = tid & 127, grp = tid >> 7;
        float s = 0.f;
        #pragma unroll 8
        for (int i = 0; i < 32; i++)
            s += d_s1p[(t * 128 + grp * 32 + i) * 128 + h];
        r[tid] = s; __syncthreads();
        if (tid < 128) s1sm[tid] = r[tid] + r[tid + 128] + r[tid + 256] + r[tid + 384];
        __syncthreads();
    }

    // sb for h in [q*32, q*32+32)
    {
        const int hl = tid & 31, dgrp = tid >> 5;   // 16 groups x 8 d
        float sbp = 0.f;
        #pragma unroll
        for (int i = 0; i < 8; i++) {
            int d = dgrp * 8 + i;
            sbp = fmaf(s1sm[d], B2[t * 16384 + d * 128 + q * 32 + hl], sbp);
        }
        r[dgrp * 32 + hl] = sbp;
        __syncthreads();
        if (tid < 256) r[tid] += r[tid + 256];
        __syncthreads();
        if (tid < 128) r[tid] += r[tid + 128];
        __syncthreads();
        if (tid < 64) r[tid] += r[tid + 64];
        __syncthreads();
        if (tid < 32) d_sb[t * 128 + q * 32 + tid] = r[tid] + r[tid + 32];
    }
}

// ---------------- K4: layer2 fp16 HMMA, smem-staged C2  grid (128, 2, T), block 256 ----------------
// block: 16 e's (x chunk) x 64 h's (y half); warp w covers h-tile w*8..w*8+8
__global__ __launch_bounds__(256) void k_l2() {
    __shared__ __align__(16) unsigned g1b[16 * 68];
    __shared__ __align__(16) unsigned g1r[16 * 68];
    __shared__ __align__(16) unsigned c2bs[64 * 68];
    __shared__ __align__(16) unsigned c2rs[64 * 68];
    __shared__ float sbs[64];

    const int tid = threadIdx.x;
    const int chunk = blockIdx.x, hhalf = blockIdx.y, t = blockIdx.z;
    const int e0 = chunk * 16, hb = hhalf * 64;

    // stage g1 (scaled, split)
    const float2* gsrc = reinterpret_cast<const float2*>(d_g1 + (size_t)(t * EE + e0) * 128);
    for (int i = tid; i < 1024; i += 256) {
        int e = i >> 6, j = i & 63;
        float2 v = gsrc[e * 64 + j];
        float v0 = v.x * G1SC, v1 = v.y * G1SC;
        __half b0 = __float2half_rn(v0), b1 = __float2half_rn(v1);
        __half2 big = __halves2half2(b0, b1);
        __half2 res = __halves2half2(__float2half_rn(v0 - __half2float(b0)),
                                     __float2half_rn(v1 - __half2float(b1)));
        g1b[e * 68 + j] = h2bits(big);
        g1r[e * 68 + j] = h2bits(res);
    }
    // stage C2 slice (64 h)
    {
        const unsigned* cb = reinterpret_cast<const unsigned*>(d_c2b) + t * 8192 + hb * 64;
        const unsigned* cr = reinterpret_cast<const unsigned*>(d_c2r) + t * 8192 + hb * 64;
        for (int i = tid; i < 4096; i += 256) {
            int hl = i >> 6, dw = i & 63;
            c2bs[hl * 68 + dw] = cb[hl * 64 + dw];
            c2rs[hl * 68 + dw] = cr[hl * 64 + dw];
        }
    }
    if (tid < 64) sbs[tid] = d_sb[t * 128 + hb + tid];
    __syncthreads();

    const int lane = tid & 31, wrp = tid >> 5;
    const int g = lane >> 2, tq = lane & 3;

    float acc[4] = {0.f, 0.f, 0.f, 0.f};

    #pragma unroll
    for (int kb = 0; kb < 8; kb++) {
        const int aw = kb * 8 + tq;
        unsigned a0 = g1b[g * 68 + aw],       a1 = g1b[(g + 8) * 68 + aw];
        unsigned a2 = g1b[g * 68 + aw + 4],   a3 = g1b[(g + 8) * 68 + aw + 4];
        unsigned r0 = g1r[g * 68 + aw],       r1 = g1r[(g + 8) * 68 + aw];
        unsigned r2 = g1r[g * 68 + aw + 4],   r3 = g1r[(g + 8) * 68 + aw + 4];
        const int hl = wrp * 8 + g;
        unsigned b0 = c2bs[hl * 68 + aw], b1 = c2bs[hl * 68 + aw + 4];
        unsigned q0 = c2rs[hl * 68 + aw], q1 = c2rs[hl * 68 + aw + 4];
        mma_f16(acc, a0, a1, a2, a3, b0, b1);   // gb*Cb
        mma_f16(acc, a0, a1, a2, a3, q0, q1);   // gb*Cr
        mma_f16(acc, r0, r1, r2, r3, b0, b1);   // gr*Cb
    }

    // max over 16 e's, unscale, add sb, relu, atomicMax
    float m0 = fmaxf(acc[0], acc[2]);
    float m1 = fmaxf(acc[1], acc[3]);
    #pragma unroll
    for (int off = 4; off < 32; off <<= 1) {
        m0 = fmaxf(m0, __shfl_xor_sync(0xffffffffu, m0, off));
        m1 = fmaxf(m1, __shfl_xor_sync(0xffffffffu, m1, off));
    }
    if (g == 0) {
        int hl = wrp * 8 + tq * 2;
        atomicMax(&d_gmax[t * 128 + hb + hl],
                  __float_as_int(fmaxf(fmaf(m0, G1SCI, sbs[hl]), 0.f)));
        atomicMax(&d_gmax[t * 128 + hb + hl + 1],
                  __float_as_int(fmaxf(fmaf(m1, G1SCI, sbs[hl + 1]), 0.f)));
    }
}

// ---------------- K5: gf + final matmul partials  grid 8, block 256 ----------------
__global__ __launch_bounds__(256) void k_gfw(const float* __restrict__ Aout,
                                             const float* __restrict__ Wm)
{
    __shared__ float gv[512];
    __shared__ float gfs[64];
    __shared__ float r[256];
    const int tid = threadIdx.x, blk = blockIdx.x;

    for (int i = tid; i < 512; i += 256) gv[i] = __int_as_float(d_gmax[i]);
    __syncthreads();

    const int j = tid >> 2, sub = tid & 3;
    const int gi = blk * 64 + j;
    const int t2 = gi >> 7, o = gi & 127;
    float a = 0.f;
    #pragma unroll 4
    for (int k = 0; k < 32; k++)
        a = fmaf(gv[t2 * 128 + sub * 32 + k],
                 Aout[t2 * 16384 + (sub * 32 + k) * 128 + o], a);
    r[tid] = a;
    __syncthreads();
    if (sub == 0) gfs[j] = r[tid] + r[tid + 1] + r[tid + 2] + r[tid + 3];
    __syncthreads();

    float acc = 0.f;
    const int i0 = blk * 64;
    #pragma unroll 8
    for (int i = 0; i < 64; i++)
        acc = fmaf(gfs[i], Wm[(i0 + i) * 256 + tid], acc);
    d_fpart[blk * 256 + tid] = acc;
}

// ---------------- K6: combine  grid 1, block 256 ----------------
__global__ void k_fin2(const float* __restrict__ bm, float* __restrict__ out) {
    const int tid = threadIdx.x;
    float a = bm[tid];
    #pragma unroll
    for (int b = 0; b < 8; b++) a += d_fpart[b * 256 + tid];
    out[tid] = a;
}

// ---------------- launch ----------------
extern "C" void kernel_launch(void* const* d_in, const int* in_sizes, int n_in,
                              void* d_out, int out_size)
{
    const float* points = (const float*)d_in[0];
    const float* w1     = (const float*)d_in[1];
    const float* b1     = (const float*)d_in[2];
    const float* w2     = (const float*)d_in[3];
    const float* b2     = (const float*)d_in[4];
    const float* A1     = (const float*)d_in[5];
    const float* B1     = (const float*)d_in[6];
    const float* A2     = (const float*)d_in[7];
    const float* B2     = (const float*)d_in[8];
    const float* Aout   = (const float*)d_in[9];
    const float* Wm     = (const float*)d_in[10];
    const float* bm     = (const float*)d_in[11];
    float* out = (float*)d_out;

    k_prep<<<dim3(16, TT), 256>>>(A2, B2);
    k_conv<<<dim3(EE / 2, TT), 128>>>(points, w1, b1, w2, b2);
    k_s0p<<<dim3(32, TT), 256>>>();
    k_l1<<<dim3(128, TT), 256>>>(A1, B1);
    k_s1c<<<dim3(4, TT), 512>>>(B2);
    k_l2<<<dim3(128, 2, TT), 256>>>();
    k_gfw<<<8, 256>>>(Aout, Wm);
    k_fin2<<<1, 256>>>(bm, out);
}